// round 2
// baseline (speedup 1.0000x reference)
#include <cuda_runtime.h>

// ---------------------------------------------------------------------------
// SuperpixelAttention on GB300 — Round 1 fp32 baseline
//   x[T,C,H,W], sims[T,S,H,W], W* [C,C]  ->  out[T,C,H,W]
//   T=4, C=256, H=W=256, S=9, NH=4, hd=64, 5x5 window (25 taps)
//
// Pipeline:
//   K1 qkv_kernel : q/k/v = xp @ W{q,k,v}   (q scaled by hd^-0.5)   -> scratch [pix][C]
//   K2 attn_kernel: 25-tap neighborhood attention w/ superpixel reweight -> o [pix][C]
//   K3 proj_kernel: out = o @ Wp, stored transposed to [T,C,H,W]
// ---------------------------------------------------------------------------

#define NPIX 262144              // T*H*W
#define NELEM 67108864           // NPIX * 256

__device__ float g_q[NELEM];
__device__ float g_k[NELEM];
__device__ float g_v[NELEM];
__device__ float g_o[NELEM];

// ---------------------------------------------------------------------------
// K1: QKV projection.
// Block = 64 pixels (one aligned row segment, never crosses a (t,h) row since
// 64 | 256). 256 threads. x tile staged in smem as xs[c][p] (pitch 68).
// For each matrix m and 32-wide output-channel chunk: stage W[:,n0:n0+32] in
// smem, thread (nl = tid&31 -> out channel, pg = tid>>5 -> 8 pixels) keeps
// 8 fp32 accumulators. Inner loop: 1 conflict-free LDS + 2 broadcast LDS.128
// + 8 FFMA.
// ---------------------------------------------------------------------------
__global__ void __launch_bounds__(256) qkv_kernel(
    const float* __restrict__ x,
    const float* __restrict__ Wq,
    const float* __restrict__ Wk,
    const float* __restrict__ Wv) {
  extern __shared__ float xs[];          // 256 * 68 floats
  __shared__ float ws[256 * 32];

  const int tid  = threadIdx.x;
  const int pix0 = blockIdx.x * 64;
  const int t    = pix0 >> 16;
  const int h    = (pix0 >> 8) & 255;
  const int w0   = pix0 & 255;           // multiple of 64
  const int base = t * 16777216 + h * 256 + w0;

  // stage x tile: read x[t][c][h][w0+p] coalesced, write xs[c*68+p] (no conflicts)
  for (int i = tid; i < 16384; i += 256) {
    int c = i >> 6, p = i & 63;
    xs[c * 68 + p] = x[base + c * 65536 + p];
  }
  __syncthreads();

  const int nl = tid & 31;
  const int pg = tid >> 5;
  const float4* xsp = (const float4*)(xs + pg * 8);   // 32B aligned

  const float* Wm[3] = {Wq, Wk, Wv};
  float*       Bm[3] = {g_q, g_k, g_v};

  for (int m = 0; m < 3; ++m) {
    const float* Wmat = Wm[m];
    float*       buf  = Bm[m];
    const float  sc   = (m == 0) ? 0.125f : 1.0f;     // hd^-0.5 on q

    for (int n0 = 0; n0 < 256; n0 += 32) {
      __syncthreads();
      for (int i = tid; i < 8192; i += 256)
        ws[i] = Wmat[(i >> 5) * 256 + n0 + (i & 31)];
      __syncthreads();

      float a0 = 0.f, a1 = 0.f, a2 = 0.f, a3 = 0.f;
      float a4 = 0.f, a5 = 0.f, a6 = 0.f, a7 = 0.f;
#pragma unroll 4
      for (int c = 0; c < 256; ++c) {
        float  wv = ws[c * 32 + nl];     // conflict-free (lanes -> consecutive banks)
        float4 xa = xsp[c * 17];         // 68/4 = 17; broadcast within warp
        float4 xb = xsp[c * 17 + 1];
        a0 += wv * xa.x; a1 += wv * xa.y; a2 += wv * xa.z; a3 += wv * xa.w;
        a4 += wv * xb.x; a5 += wv * xb.y; a6 += wv * xb.z; a7 += wv * xb.w;
      }
      int ob = (pix0 + pg * 8) * 256 + n0 + nl;        // 128B-coalesced per pixel
      buf[ob]           = a0 * sc;
      buf[ob + 256]     = a1 * sc;
      buf[ob + 2 * 256] = a2 * sc;
      buf[ob + 3 * 256] = a3 * sc;
      buf[ob + 4 * 256] = a4 * sc;
      buf[ob + 5 * 256] = a5 * sc;
      buf[ob + 6 * 256] = a6 * sc;
      buf[ob + 7 * 256] = a7 * sc;
    }
  }
}

// ---------------------------------------------------------------------------
// K2: neighborhood attention. 1 block per pixel, 128 threads.
// Thread tid owns channels {2*tid, 2*tid+1}; warp == head (64 ch / head).
// ---------------------------------------------------------------------------
__device__ __forceinline__ float warp_sum(float v) {
  v += __shfl_xor_sync(0xffffffffu, v, 16);
  v += __shfl_xor_sync(0xffffffffu, v, 8);
  v += __shfl_xor_sync(0xffffffffu, v, 4);
  v += __shfl_xor_sync(0xffffffffu, v, 2);
  v += __shfl_xor_sync(0xffffffffu, v, 1);
  return v;
}
__device__ __forceinline__ float warp_max(float v) {
  v = fmaxf(v, __shfl_xor_sync(0xffffffffu, v, 16));
  v = fmaxf(v, __shfl_xor_sync(0xffffffffu, v, 8));
  v = fmaxf(v, __shfl_xor_sync(0xffffffffu, v, 4));
  v = fmaxf(v, __shfl_xor_sync(0xffffffffu, v, 2));
  v = fmaxf(v, __shfl_xor_sync(0xffffffffu, v, 1));
  return v;
}

__global__ void __launch_bounds__(128) attn_kernel(const float* __restrict__ sims) {
  const int pix = blockIdx.x;
  const int tid = threadIdx.x;
  const int w = pix & 255, h = (pix >> 8) & 255, t = pix >> 16;

  const float2* q2 = (const float2*)g_q;
  const float2* k2 = (const float2*)g_k;
  const float2* v2 = (const float2*)g_v;
  float2*       o2 = (float2*)g_o;

  __shared__ float ssim[9];
  __shared__ int   nb[25];
  __shared__ float simdot[25];
  __shared__ float logits[4][25];
  __shared__ float wts[4][32];

  if (tid < 9)
    ssim[tid] = sims[((t * 9 + tid) << 16) + (pix & 65535)];
  if (tid < 25) {
    int di = tid / 5 - 2;
    int dj = tid - (tid / 5) * 5 - 2;
    int ii = min(max(h + di, 0), 255);
    int jj = min(max(w + dj, 0), 255);
    nb[tid] = (t << 16) + (ii << 8) + jj;
  }
  __syncthreads();

  const float2 qr = q2[pix * 128 + tid];

  // superpixel similarity dot (S=9) per tap — warp 0 lanes 0..24
  if (tid < 25) {
    int hw = nb[tid] & 65535;
    float sd = 0.f;
#pragma unroll
    for (int s = 0; s < 9; ++s)
      sd += ssim[s] * sims[((t * 9 + s) << 16) + hw];
    simdot[tid] = sd;
  }

  const int lane = tid & 31, head = tid >> 5;

  // q.k logits per tap, per head (warp == head)
#pragma unroll
  for (int kk = 0; kk < 25; ++kk) {
    float2 kr = k2[nb[kk] * 128 + tid];
    float  s  = warp_sum(qr.x * kr.x + qr.y * kr.y);
    if (lane == 0) logits[head][kk] = s;
  }
  __syncthreads();

  // exp-shift, reweight by sim, renormalize (per head, lane -> tap)
  {
    float a  = (lane < 25) ? logits[head][lane] : -1e30f;
    float mx = warp_max(a);
    float e  = (lane < 25) ? expf(a - mx) * simdot[lane] : 0.f;
    float sm = warp_sum(e);
    wts[head][lane] = e / (1e-10f + sm);
  }
  __syncthreads();

  float2 acc = make_float2(0.f, 0.f);
#pragma unroll
  for (int kk = 0; kk < 25; ++kk) {
    float  wgt = wts[head][kk];
    float2 vr  = v2[nb[kk] * 128 + tid];
    acc.x += wgt * vr.x;
    acc.y += wgt * vr.y;
  }
  o2[pix * 128 + tid] = acc;
}

// ---------------------------------------------------------------------------
// K3: output projection o @ Wp with transposed store to [T,C,H,W].
// Same GEMM structure as K1; the o tile is transposed into smem on load
// (coalesced global reads, 4-way-conflicted smem writes — negligible), and
// results are staged through ys[n][p] so global stores are 256B-coalesced
// rows along w.
// ---------------------------------------------------------------------------
__global__ void __launch_bounds__(256) proj_kernel(
    const float* __restrict__ Wp, float* __restrict__ y) {
  extern __shared__ float xs[];          // 256 * 68 floats
  __shared__ float ws[256 * 32];
  __shared__ float ys[32 * 65];

  const int tid  = threadIdx.x;
  const int pix0 = blockIdx.x * 64;
  const int t    = pix0 >> 16;
  const int h    = (pix0 >> 8) & 255;
  const int w0   = pix0 & 255;

  // stage o tile transposed: read o[p][c] coalesced along c, write xs[c][p]
  for (int i = tid; i < 16384; i += 256) {
    int p = i >> 8, c = i & 255;
    xs[c * 68 + p] = g_o[(pix0 + p) * 256 + c];
  }
  __syncthreads();

  const int nl = tid & 31;
  const int pg = tid >> 5;
  const float4* xsp = (const float4*)(xs + pg * 8);
  const int ybase = t * 16777216 + h * 256 + w0;

  for (int n0 = 0; n0 < 256; n0 += 32) {
    __syncthreads();
    for (int i = tid; i < 8192; i += 256)
      ws[i] = Wp[(i >> 5) * 256 + n0 + (i & 31)];
    __syncthreads();

    float a0 = 0.f, a1 = 0.f, a2 = 0.f, a3 = 0.f;
    float a4 = 0.f, a5 = 0.f, a6 = 0.f, a7 = 0.f;
#pragma unroll 4
    for (int c = 0; c < 256; ++c) {
      float  wv = ws[c * 32 + nl];
      float4 xa = xsp[c * 17];
      float4 xb = xsp[c * 17 + 1];
      a0 += wv * xa.x; a1 += wv * xa.y; a2 += wv * xa.z; a3 += wv * xa.w;
      a4 += wv * xb.x; a5 += wv * xb.y; a6 += wv * xb.z; a7 += wv * xb.w;
    }
    // stage to smem [n][p] (stride 65 -> conflict-free writes)
    int yb = nl * 65 + pg * 8;
    ys[yb]     = a0; ys[yb + 1] = a1; ys[yb + 2] = a2; ys[yb + 3] = a3;
    ys[yb + 4] = a4; ys[yb + 5] = a5; ys[yb + 6] = a6; ys[yb + 7] = a7;
    __syncthreads();
    // coalesced store: each channel writes 64 consecutive w
    for (int i = tid; i < 2048; i += 256) {
      int c = i >> 6, p = i & 63;
      y[ybase + (n0 + c) * 65536 + p] = ys[c * 65 + p];
    }
  }
}

// ---------------------------------------------------------------------------
extern "C" void kernel_launch(void* const* d_in, const int* in_sizes, int n_in,
                              void* d_out, int out_size) {
  (void)in_sizes; (void)n_in; (void)out_size;
  const float* x    = (const float*)d_in[0];
  const float* sims = (const float*)d_in[1];
  // d_in[2] = flows (int32, all zeros -> temporal offset 0; unused by reference math)
  const float* Wq = (const float*)d_in[3];
  const float* Wk = (const float*)d_in[4];
  const float* Wv = (const float*)d_in[5];
  const float* Wp = (const float*)d_in[6];
  float* out = (float*)d_out;

  const int dyn = 256 * 68 * sizeof(float);  // 69632 B > 48KB default
  cudaFuncSetAttribute(qkv_kernel, cudaFuncAttributeMaxDynamicSharedMemorySize, dyn);
  cudaFuncSetAttribute(proj_kernel, cudaFuncAttributeMaxDynamicSharedMemorySize, dyn);

  qkv_kernel<<<NPIX / 64, 256, dyn>>>(x, Wq, Wk, Wv);
  attn_kernel<<<NPIX, 128>>>(sims);
  proj_kernel<<<NPIX / 64, 256, dyn>>>(Wp, out);
}

// round 5
// speedup vs baseline: 2.3969x; 2.3969x over previous
#include <cuda_runtime.h>
#include <cuda_bf16.h>
#include <cstdint>

// ---------------------------------------------------------------------------
// SuperpixelAttention GB300 — Round 4: mma.sync (HMMA) bf16 split GEMMs
// (tcgen05 is unavailable: harness PTX targets sm_103 without the 'a' suffix)
//   T=4, C=256, H=W=256, S=9, NH=4, hd=64, 5x5 window
// Pipeline:
//   conv_x : x fp32 -> g_x2 [pix][hi256|lo256] bf16
//   conv_w : Wq|Wk|Wv -> g_w1 [768][hi|lo] (q scale folded), Wp -> g_w2
//   gemm(0): q/k/v fp32   (M=262144, N=768, K'=768 via 3-term split)
//   attn   : 25-tap neighborhood attention
//   conv_o : o fp32 -> g_o2 bf16 hi|lo
//   gemm(1): out = o @ Wp, transposed store to [T,C,H,W]
// ---------------------------------------------------------------------------

#define NPIX 262144
#define NELEM 67108864

__device__ float g_q[NELEM];
__device__ float g_k[NELEM];
__device__ float g_v[NELEM];
__device__ float g_o[NELEM];
__device__ __nv_bfloat16 g_x2[NPIX * 512];
__device__ __nv_bfloat16 g_o2[NPIX * 512];
__device__ __nv_bfloat16 g_w1[768 * 512];
__device__ __nv_bfloat16 g_w2[256 * 512];

__device__ __forceinline__ uint32_t smem_u32(const void* p) {
  uint32_t a;
  asm("{ .reg .u64 t; cvta.to.shared.u64 t, %1; cvt.u32.u64 %0, t; }"
      : "=r"(a) : "l"(p));
  return a;
}
#define SW128(o) ((o) ^ (((o) >> 3) & 0x70))

__device__ __forceinline__ void ldsm4(uint32_t& r0, uint32_t& r1, uint32_t& r2,
                                      uint32_t& r3, uint32_t a) {
  asm volatile("ldmatrix.sync.aligned.m8n8.x4.shared.b16 {%0,%1,%2,%3}, [%4];"
               : "=r"(r0), "=r"(r1), "=r"(r2), "=r"(r3) : "r"(a));
}
__device__ __forceinline__ void mma16816(float* c, const uint32_t* a,
                                         const uint32_t* b) {
  asm volatile(
      "mma.sync.aligned.m16n8k16.row.col.f32.bf16.bf16.f32 "
      "{%0,%1,%2,%3},{%4,%5,%6,%7},{%8,%9},{%0,%1,%2,%3};"
      : "+f"(c[0]), "+f"(c[1]), "+f"(c[2]), "+f"(c[3])
      : "r"(a[0]), "r"(a[1]), "r"(a[2]), "r"(a[3]), "r"(b[0]), "r"(b[1]));
}
__device__ __forceinline__ void cp16(uint32_t s, const void* g) {
  asm volatile("cp.async.cg.shared.global [%0], [%1], 16;" :: "r"(s), "l"(g));
}

// ---------------------------------------------------------------------------
// Conversions
// ---------------------------------------------------------------------------
__global__ void __launch_bounds__(256) conv_x(const float* __restrict__ x) {
  extern __shared__ float xs[];  // 256 * 65
  const int tid = threadIdx.x;
  const int pix0 = blockIdx.x * 64;
  const int t = pix0 >> 16, h = (pix0 >> 8) & 255, w0 = pix0 & 255;
  const size_t base = (size_t)t * 16777216 + h * 256 + w0;
  for (int i = tid; i < 16384; i += 256) {
    int c = i >> 6, p = i & 63;
    xs[c * 65 + p] = x[base + (size_t)c * 65536 + p];
  }
  __syncthreads();
  for (int i = tid; i < 32768; i += 256) {
    int p = i >> 9, kk = i & 511, c = kk & 255;
    float v = xs[c * 65 + p];
    __nv_bfloat16 hi = __float2bfloat16_rn(v);
    __nv_bfloat16 o = (kk < 256) ? hi : __float2bfloat16_rn(v - __bfloat162float(hi));
    g_x2[(size_t)(pix0 + p) * 512 + kk] = o;
  }
}

__global__ void __launch_bounds__(256) conv_w(const float* __restrict__ Wq,
                                              const float* __restrict__ Wk,
                                              const float* __restrict__ Wv,
                                              const float* __restrict__ Wp) {
  const int n = blockIdx.x;   // 0..1023
  const int c = threadIdx.x;
  float v;
  __nv_bfloat16* dst;
  if (n < 768) {
    const float* Wm = (n < 256) ? Wq : ((n < 512) ? Wk : Wv);
    v = Wm[c * 256 + (n & 255)];
    if (n < 256) v *= 0.125f;  // fold hd^-0.5 into Wq
    dst = g_w1 + (size_t)n * 512;
  } else {
    v = Wp[c * 256 + (n & 255)];
    dst = g_w2 + (size_t)(n - 768) * 512;
  }
  __nv_bfloat16 hi = __float2bfloat16_rn(v);
  dst[c] = hi;
  dst[256 + c] = __float2bfloat16_rn(v - __bfloat162float(hi));
}

__global__ void __launch_bounds__(1024) conv_o() {
  const int pix = blockIdx.x * 4 + (threadIdx.x >> 8);
  const int c = threadIdx.x & 255;
  float v = g_o[(size_t)pix * 256 + c];
  __nv_bfloat16 hi = __float2bfloat16_rn(v);
  g_o2[(size_t)pix * 512 + c] = hi;
  g_o2[(size_t)pix * 512 + 256 + c] = __float2bfloat16_rn(v - __bfloat162float(hi));
}

// ---------------------------------------------------------------------------
// mma.sync GEMM: block = 128 pixels (M) x 128 outputs (N-chunk).
// A slice (128 x 512 bf16, SW128, 8 chunks of [128][64]) resident in smem.
// B streamed per 64-K chunk via cp.async double buffer.
// K loop: 12 chunks = 3 split terms x 4. 8 warps: warp tile m64 x n32.
// mode 0: B=g_w1, 6 N-chunks -> q|k|v.  mode 1: B=g_w2, 2 N-chunks -> y.
// ---------------------------------------------------------------------------
__global__ void __launch_bounds__(256) gemm_kernel(
    const __nv_bfloat16* __restrict__ A2,
    const __nv_bfloat16* __restrict__ B2,
    float* __restrict__ y, int mode) {
  extern __shared__ char dsm[];
  char* base = (char*)((((uintptr_t)dsm) + 1023) & ~(uintptr_t)1023);
  const uint32_t As_a = smem_u32(base);
  const uint32_t Bs_a0 = As_a + 131072u;
  float* ys = (float*)(base + 163840);

  const int tid = threadIdx.x, lane = tid & 31, wid = tid >> 5;
  const int wm = wid & 1, wn = wid >> 1;
  const int pix0 = blockIdx.x * 128;

  // stage A: 8 chunks of [128 rows][128B] with SW128
  const uint4* Aq = (const uint4*)A2;
  for (int idx = tid; idx < 8192; idx += 256) {
    int ch = idx >> 10, row = (idx >> 3) & 127, c = idx & 7;
    *(uint4*)(base + ch * 16384 + SW128((uint32_t)(row * 128 + c * 16))) =
        Aq[(size_t)(pix0 + row) * 64 + ch * 8 + c];
  }

  const uint4* Bq = (const uint4*)B2;
  const int total = (mode ? 2 : 6) * 12;

  auto prefetchB = [&](int q) {
    int kc2 = q % 12, term = kc2 >> 2;
    int n0g = (q / 12) << 7;
    int b8 = ((term == 1) ? 32 : 0) + (kc2 & 3) * 8;
    uint32_t buf = Bs_a0 + (uint32_t)((q & 1) << 14);
    for (int idx = tid; idx < 1024; idx += 256) {
      int row = idx >> 3, c = idx & 7;
      cp16(buf + SW128((uint32_t)(row * 128 + c * 16)),
           &Bq[(size_t)(n0g + row) * 64 + b8 + c]);
    }
    asm volatile("cp.async.commit_group;" ::: "memory");
  };

  float acc[4][4][4];
#pragma unroll
  for (int i = 0; i < 4; i++)
#pragma unroll
    for (int j = 0; j < 4; j++)
#pragma unroll
      for (int r = 0; r < 4; r++) acc[i][j][r] = 0.f;

  prefetchB(0);

  const int arow_off = (lane & 7) + ((lane >> 3) & 1) * 8;
  const int ak_ex = ((lane >> 4) & 1) * 16;
  const int brow_off = (lane & 7) + ((lane >> 4) & 1) * 8;
  const int bk_ex = ((lane >> 3) & 1) * 16;

  for (int q = 0; q < total; ++q) {
    if (q + 1 < total) {
      prefetchB(q + 1);
      asm volatile("cp.async.wait_group 1;" ::: "memory");
    } else {
      asm volatile("cp.async.wait_group 0;" ::: "memory");
    }
    __syncthreads();  // B chunk q visible (and A tile on q==0)

    const int kc2 = q % 12, term = kc2 >> 2;
    const uint32_t Ab = As_a + (uint32_t)((((term == 2) ? 4 : 0) + (kc2 & 3)) * 16384);
    const uint32_t Bb = Bs_a0 + (uint32_t)((q & 1) << 14);

#pragma unroll
    for (int s = 0; s < 4; ++s) {
      uint32_t af[4][4];
#pragma unroll
      for (int i = 0; i < 4; ++i) {
        uint32_t off = (uint32_t)((wm * 64 + i * 16 + arow_off) * 128 + s * 32 + ak_ex);
        ldsm4(af[i][0], af[i][1], af[i][2], af[i][3], Ab + SW128(off));
      }
      uint32_t bf[4][2];
#pragma unroll
      for (int j2 = 0; j2 < 2; ++j2) {
        uint32_t off = (uint32_t)((wn * 32 + j2 * 16 + brow_off) * 128 + s * 32 + bk_ex);
        ldsm4(bf[2 * j2][0], bf[2 * j2][1], bf[2 * j2 + 1][0], bf[2 * j2 + 1][1],
              Bb + SW128(off));
      }
#pragma unroll
      for (int i = 0; i < 4; ++i)
#pragma unroll
        for (int j = 0; j < 4; ++j) mma16816(acc[i][j], af[i], bf[j]);
    }

    if (kc2 == 11) {  // epilogue for this N-chunk
      const int nc = q / 12;
      if (mode == 0) {
        float* dst = (nc < 2) ? g_q : (nc < 4) ? g_k : g_v;
        const int colb = (nc & 1) * 128 + wn * 32;
#pragma unroll
        for (int i = 0; i < 4; ++i) {
          int row0 = pix0 + wm * 64 + i * 16 + (lane >> 2);
#pragma unroll
          for (int j = 0; j < 4; ++j) {
            int col = colb + j * 8 + 2 * (lane & 3);
            *(float2*)(dst + (size_t)row0 * 256 + col) =
                make_float2(acc[i][j][0], acc[i][j][1]);
            *(float2*)(dst + (size_t)(row0 + 8) * 256 + col) =
                make_float2(acc[i][j][2], acc[i][j][3]);
          }
        }
      } else {
        const int t = pix0 >> 16, h = (pix0 >> 8) & 255, w0 = pix0 & 255;
        float* yb = y + (size_t)t * 16777216 + h * 256 + w0;
        for (int g = 0; g < 4; ++g) {   // stage 32 channels at a time
          if (wn == g) {
#pragma unroll
            for (int i = 0; i < 4; ++i) {
              int row0 = wm * 64 + i * 16 + (lane >> 2);
#pragma unroll
              for (int j = 0; j < 4; ++j) {
                int cl = j * 8 + 2 * (lane & 3);
                ys[cl * 132 + row0] = acc[i][j][0];
                ys[(cl + 1) * 132 + row0] = acc[i][j][1];
                ys[cl * 132 + row0 + 8] = acc[i][j][2];
                ys[(cl + 1) * 132 + row0 + 8] = acc[i][j][3];
              }
            }
          }
          __syncthreads();
          const int chb = nc * 128 + g * 32;
          for (int idx = tid; idx < 4096; idx += 256) {
            int cl = idx >> 7, p = idx & 127;
            yb[(size_t)(chb + cl) * 65536 + p] = ys[cl * 132 + p];
          }
          __syncthreads();
        }
      }
#pragma unroll
      for (int i = 0; i < 4; i++)
#pragma unroll
        for (int j = 0; j < 4; j++)
#pragma unroll
          for (int r = 0; r < 4; r++) acc[i][j][r] = 0.f;
    }
    __syncthreads();  // protect B buffer reuse
  }
}

// ---------------------------------------------------------------------------
// Attention: 1 block/pixel, 128 threads, warp == head
// ---------------------------------------------------------------------------
__device__ __forceinline__ float warp_sum(float v) {
  v += __shfl_xor_sync(0xffffffffu, v, 16);
  v += __shfl_xor_sync(0xffffffffu, v, 8);
  v += __shfl_xor_sync(0xffffffffu, v, 4);
  v += __shfl_xor_sync(0xffffffffu, v, 2);
  v += __shfl_xor_sync(0xffffffffu, v, 1);
  return v;
}
__device__ __forceinline__ float warp_max(float v) {
  v = fmaxf(v, __shfl_xor_sync(0xffffffffu, v, 16));
  v = fmaxf(v, __shfl_xor_sync(0xffffffffu, v, 8));
  v = fmaxf(v, __shfl_xor_sync(0xffffffffu, v, 4));
  v = fmaxf(v, __shfl_xor_sync(0xffffffffu, v, 2));
  v = fmaxf(v, __shfl_xor_sync(0xffffffffu, v, 1));
  return v;
}

__global__ void __launch_bounds__(128) attn_kernel(const float* __restrict__ sims) {
  const int pix = blockIdx.x;
  const int tid = threadIdx.x;
  const int w = pix & 255, h = (pix >> 8) & 255, t = pix >> 16;

  const float2* q2 = (const float2*)g_q;
  const float2* k2 = (const float2*)g_k;
  const float2* v2 = (const float2*)g_v;
  float2* o2 = (float2*)g_o;

  __shared__ float ssim[9];
  __shared__ int nb[25];
  __shared__ float simdot[25];
  __shared__ float logits[4][25];
  __shared__ float wts[4][32];

  if (tid < 9) ssim[tid] = sims[((t * 9 + tid) << 16) + (pix & 65535)];
  if (tid < 25) {
    int di = tid / 5 - 2;
    int dj = tid - (tid / 5) * 5 - 2;
    int ii = min(max(h + di, 0), 255);
    int jj = min(max(w + dj, 0), 255);
    nb[tid] = (t << 16) + (ii << 8) + jj;
  }
  __syncthreads();

  const float2 qr = q2[pix * 128 + tid];

  if (tid < 25) {
    int hw = nb[tid] & 65535;
    float sd = 0.f;
#pragma unroll
    for (int s = 0; s < 9; ++s) sd += ssim[s] * sims[((t * 9 + s) << 16) + hw];
    simdot[tid] = sd;
  }

  const int lane = tid & 31, head = tid >> 5;
#pragma unroll
  for (int kk = 0; kk < 25; ++kk) {
    float2 kr = k2[nb[kk] * 128 + tid];
    float s = warp_sum(qr.x * kr.x + qr.y * kr.y);
    if (lane == 0) logits[head][kk] = s;
  }
  __syncthreads();
  {
    float a = (lane < 25) ? logits[head][lane] : -1e30f;
    float mx = warp_max(a);
    float e = (lane < 25) ? expf(a - mx) * simdot[lane] : 0.f;
    float sm = warp_sum(e);
    wts[head][lane] = e / (1e-10f + sm);
  }
  __syncthreads();

  float2 acc = make_float2(0.f, 0.f);
#pragma unroll
  for (int kk = 0; kk < 25; ++kk) {
    float wgt = wts[head][kk];
    float2 vr = v2[nb[kk] * 128 + tid];
    acc.x += wgt * vr.x;
    acc.y += wgt * vr.y;
  }
  o2[pix * 128 + tid] = acc;
}

// ---------------------------------------------------------------------------
extern "C" void kernel_launch(void* const* d_in, const int* in_sizes, int n_in,
                              void* d_out, int out_size) {
  (void)in_sizes; (void)n_in; (void)out_size;
  const float* x = (const float*)d_in[0];
  const float* sims = (const float*)d_in[1];
  const float* Wq = (const float*)d_in[3];
  const float* Wk = (const float*)d_in[4];
  const float* Wv = (const float*)d_in[5];
  const float* Wp = (const float*)d_in[6];
  float* out = (float*)d_out;

  const int smem_cx = 256 * 65 * sizeof(float);
  const int smem_gm = 1024 + 163840 + 16896;  // align + A(128K)+B(2x16K) + ys
  cudaFuncSetAttribute(conv_x, cudaFuncAttributeMaxDynamicSharedMemorySize, smem_cx);
  cudaFuncSetAttribute(gemm_kernel, cudaFuncAttributeMaxDynamicSharedMemorySize, smem_gm);

  __nv_bfloat16 *px2, *po2, *pw1, *pw2;
  cudaGetSymbolAddress((void**)&px2, g_x2);
  cudaGetSymbolAddress((void**)&po2, g_o2);
  cudaGetSymbolAddress((void**)&pw1, g_w1);
  cudaGetSymbolAddress((void**)&pw2, g_w2);

  conv_x<<<NPIX / 64, 256, smem_cx>>>(x);
  conv_w<<<1024, 256>>>(Wq, Wk, Wv, Wp);
  gemm_kernel<<<NPIX / 128, 256, smem_gm>>>(px2, pw1, nullptr, 0);
  attn_kernel<<<NPIX, 128>>>(sims);
  conv_o<<<NPIX / 4, 1024>>>();
  gemm_kernel<<<NPIX / 128, 256, smem_gm>>>(po2, pw2, out, 1);
}

// round 6
// speedup vs baseline: 2.6809x; 1.1185x over previous
#include <cuda_runtime.h>
#include <cuda_bf16.h>
#include <cstdint>

// ---------------------------------------------------------------------------
// SuperpixelAttention GB300 — Round 5: smem-tiled halo attention
//   conv_x : x fp32 -> g_x2 [pix][hi256|lo256] bf16
//   conv_w : Wq|Wk|Wv -> g_w1 (q scale folded), Wp -> g_w2
//   gemm(0): q/k/v fp32 (mma.sync bf16 3-term split)
//   attn   : 16x4 pixel tiles, k/v halo in smem, writes g_o2 bf16 hi|lo direct
//   gemm(1): out = o @ Wp, transposed store to [T,C,H,W]
// ---------------------------------------------------------------------------

#define NPIX 262144
#define NELEM 67108864

__device__ float g_q[NELEM];
__device__ float g_k[NELEM];
__device__ float g_v[NELEM];
__device__ __nv_bfloat16 g_x2[NPIX * 512];
__device__ __nv_bfloat16 g_o2[NPIX * 512];
__device__ __nv_bfloat16 g_w1[768 * 512];
__device__ __nv_bfloat16 g_w2[256 * 512];

__device__ __forceinline__ uint32_t smem_u32(const void* p) {
  uint32_t a;
  asm("{ .reg .u64 t; cvta.to.shared.u64 t, %1; cvt.u32.u64 %0, t; }"
      : "=r"(a) : "l"(p));
  return a;
}
#define SW128(o) ((o) ^ (((o) >> 3) & 0x70))

__device__ __forceinline__ void ldsm4(uint32_t& r0, uint32_t& r1, uint32_t& r2,
                                      uint32_t& r3, uint32_t a) {
  asm volatile("ldmatrix.sync.aligned.m8n8.x4.shared.b16 {%0,%1,%2,%3}, [%4];"
               : "=r"(r0), "=r"(r1), "=r"(r2), "=r"(r3) : "r"(a));
}
__device__ __forceinline__ void mma16816(float* c, const uint32_t* a,
                                         const uint32_t* b) {
  asm volatile(
      "mma.sync.aligned.m16n8k16.row.col.f32.bf16.bf16.f32 "
      "{%0,%1,%2,%3},{%4,%5,%6,%7},{%8,%9},{%0,%1,%2,%3};"
      : "+f"(c[0]), "+f"(c[1]), "+f"(c[2]), "+f"(c[3])
      : "r"(a[0]), "r"(a[1]), "r"(a[2]), "r"(a[3]), "r"(b[0]), "r"(b[1]));
}
__device__ __forceinline__ void cp16(uint32_t s, const void* g) {
  asm volatile("cp.async.cg.shared.global [%0], [%1], 16;" :: "r"(s), "l"(g));
}

// ---------------------------------------------------------------------------
// Conversions
// ---------------------------------------------------------------------------
__global__ void __launch_bounds__(256) conv_x(const float* __restrict__ x) {
  extern __shared__ float xs[];  // 256 * 65
  const int tid = threadIdx.x;
  const int pix0 = blockIdx.x * 64;
  const int t = pix0 >> 16, h = (pix0 >> 8) & 255, w0 = pix0 & 255;
  const size_t base = (size_t)t * 16777216 + h * 256 + w0;
  for (int i = tid; i < 16384; i += 256) {
    int c = i >> 6, p = i & 63;
    xs[c * 65 + p] = x[base + (size_t)c * 65536 + p];
  }
  __syncthreads();
  for (int i = tid; i < 32768; i += 256) {
    int p = i >> 9, kk = i & 511, c = kk & 255;
    float v = xs[c * 65 + p];
    __nv_bfloat16 hi = __float2bfloat16_rn(v);
    __nv_bfloat16 o = (kk < 256) ? hi : __float2bfloat16_rn(v - __bfloat162float(hi));
    g_x2[(size_t)(pix0 + p) * 512 + kk] = o;
  }
}

__global__ void __launch_bounds__(256) conv_w(const float* __restrict__ Wq,
                                              const float* __restrict__ Wk,
                                              const float* __restrict__ Wv,
                                              const float* __restrict__ Wp) {
  const int n = blockIdx.x;   // 0..1023
  const int c = threadIdx.x;
  float v;
  __nv_bfloat16* dst;
  if (n < 768) {
    const float* Wm = (n < 256) ? Wq : ((n < 512) ? Wk : Wv);
    v = Wm[c * 256 + (n & 255)];
    if (n < 256) v *= 0.125f;  // fold hd^-0.5 into Wq
    dst = g_w1 + (size_t)n * 512;
  } else {
    v = Wp[c * 256 + (n & 255)];
    dst = g_w2 + (size_t)(n - 768) * 512;
  }
  __nv_bfloat16 hi = __float2bfloat16_rn(v);
  dst[c] = hi;
  dst[256 + c] = __float2bfloat16_rn(v - __bfloat162float(hi));
}

// ---------------------------------------------------------------------------
// mma.sync GEMM (unchanged from R4)
// ---------------------------------------------------------------------------
__global__ void __launch_bounds__(256) gemm_kernel(
    const __nv_bfloat16* __restrict__ A2,
    const __nv_bfloat16* __restrict__ B2,
    float* __restrict__ y, int mode) {
  extern __shared__ char dsm[];
  char* base = (char*)((((uintptr_t)dsm) + 1023) & ~(uintptr_t)1023);
  const uint32_t As_a = smem_u32(base);
  const uint32_t Bs_a0 = As_a + 131072u;
  float* ys = (float*)(base + 163840);

  const int tid = threadIdx.x, lane = tid & 31, wid = tid >> 5;
  const int wm = wid & 1, wn = wid >> 1;
  const int pix0 = blockIdx.x * 128;

  const uint4* Aq = (const uint4*)A2;
  for (int idx = tid; idx < 8192; idx += 256) {
    int ch = idx >> 10, row = (idx >> 3) & 127, c = idx & 7;
    *(uint4*)(base + ch * 16384 + SW128((uint32_t)(row * 128 + c * 16))) =
        Aq[(size_t)(pix0 + row) * 64 + ch * 8 + c];
  }

  const uint4* Bq = (const uint4*)B2;
  const int total = (mode ? 2 : 6) * 12;

  auto prefetchB = [&](int q) {
    int kc2 = q % 12, term = kc2 >> 2;
    int n0g = (q / 12) << 7;
    int b8 = ((term == 1) ? 32 : 0) + (kc2 & 3) * 8;
    uint32_t buf = Bs_a0 + (uint32_t)((q & 1) << 14);
    for (int idx = tid; idx < 1024; idx += 256) {
      int row = idx >> 3, c = idx & 7;
      cp16(buf + SW128((uint32_t)(row * 128 + c * 16)),
           &Bq[(size_t)(n0g + row) * 64 + b8 + c]);
    }
    asm volatile("cp.async.commit_group;" ::: "memory");
  };

  float acc[4][4][4];
#pragma unroll
  for (int i = 0; i < 4; i++)
#pragma unroll
    for (int j = 0; j < 4; j++)
#pragma unroll
      for (int r = 0; r < 4; r++) acc[i][j][r] = 0.f;

  prefetchB(0);

  const int arow_off = (lane & 7) + ((lane >> 3) & 1) * 8;
  const int ak_ex = ((lane >> 4) & 1) * 16;
  const int brow_off = (lane & 7) + ((lane >> 4) & 1) * 8;
  const int bk_ex = ((lane >> 3) & 1) * 16;

  for (int q = 0; q < total; ++q) {
    if (q + 1 < total) {
      prefetchB(q + 1);
      asm volatile("cp.async.wait_group 1;" ::: "memory");
    } else {
      asm volatile("cp.async.wait_group 0;" ::: "memory");
    }
    __syncthreads();

    const int kc2 = q % 12, term = kc2 >> 2;
    const uint32_t Ab = As_a + (uint32_t)((((term == 2) ? 4 : 0) + (kc2 & 3)) * 16384);
    const uint32_t Bb = Bs_a0 + (uint32_t)((q & 1) << 14);

#pragma unroll
    for (int s = 0; s < 4; ++s) {
      uint32_t af[4][4];
#pragma unroll
      for (int i = 0; i < 4; ++i) {
        uint32_t off = (uint32_t)((wm * 64 + i * 16 + arow_off) * 128 + s * 32 + ak_ex);
        ldsm4(af[i][0], af[i][1], af[i][2], af[i][3], Ab + SW128(off));
      }
      uint32_t bf[4][2];
#pragma unroll
      for (int j2 = 0; j2 < 2; ++j2) {
        uint32_t off = (uint32_t)((wn * 32 + j2 * 16 + brow_off) * 128 + s * 32 + bk_ex);
        ldsm4(bf[2 * j2][0], bf[2 * j2][1], bf[2 * j2 + 1][0], bf[2 * j2 + 1][1],
              Bb + SW128(off));
      }
#pragma unroll
      for (int i = 0; i < 4; ++i)
#pragma unroll
        for (int j = 0; j < 4; ++j) mma16816(acc[i][j], af[i], bf[j]);
    }

    if (kc2 == 11) {
      const int nc = q / 12;
      if (mode == 0) {
        float* dst = (nc < 2) ? g_q : (nc < 4) ? g_k : g_v;
        const int colb = (nc & 1) * 128 + wn * 32;
#pragma unroll
        for (int i = 0; i < 4; ++i) {
          int row0 = pix0 + wm * 64 + i * 16 + (lane >> 2);
#pragma unroll
          for (int j = 0; j < 4; ++j) {
            int col = colb + j * 8 + 2 * (lane & 3);
            *(float2*)(dst + (size_t)row0 * 256 + col) =
                make_float2(acc[i][j][0], acc[i][j][1]);
            *(float2*)(dst + (size_t)(row0 + 8) * 256 + col) =
                make_float2(acc[i][j][2], acc[i][j][3]);
          }
        }
      } else {
        const int t = pix0 >> 16, h = (pix0 >> 8) & 255, w0 = pix0 & 255;
        float* yb = y + (size_t)t * 16777216 + h * 256 + w0;
        for (int g = 0; g < 4; ++g) {
          if (wn == g) {
#pragma unroll
            for (int i = 0; i < 4; ++i) {
              int row0 = wm * 64 + i * 16 + (lane >> 2);
#pragma unroll
              for (int j = 0; j < 4; ++j) {
                int cl = j * 8 + 2 * (lane & 3);
                ys[cl * 132 + row0] = acc[i][j][0];
                ys[(cl + 1) * 132 + row0] = acc[i][j][1];
                ys[cl * 132 + row0 + 8] = acc[i][j][2];
                ys[(cl + 1) * 132 + row0 + 8] = acc[i][j][3];
              }
            }
          }
          __syncthreads();
          const int chb = nc * 128 + g * 32;
          for (int idx = tid; idx < 4096; idx += 256) {
            int cl = idx >> 7, p = idx & 127;
            yb[(size_t)(chb + cl) * 65536 + p] = ys[cl * 132 + p];
          }
          __syncthreads();
        }
      }
#pragma unroll
      for (int i = 0; i < 4; i++)
#pragma unroll
        for (int j = 0; j < 4; j++)
#pragma unroll
          for (int r = 0; r < 4; r++) acc[i][j][r] = 0.f;
    }
    __syncthreads();
  }
}

// ---------------------------------------------------------------------------
// Tiled attention: block = 16(w) x 4(h) pixels, 512 threads (16 warps).
// Halo 20x8 rows (k then v, 160KB) in smem. Warp = (row r, 4-px segment seg);
// lane owns 8 channels (head = lane>>3). Writes g_o2 bf16 hi|lo directly.
// smem floats: halo 40960 | logits/wts 64*4*26 | simdot 64*26 | sims 9*160
// ---------------------------------------------------------------------------
__device__ __forceinline__ uint32_t packbf2(float a, float b) {
  __nv_bfloat162 h = __floats2bfloat162_rn(a, b);
  return *reinterpret_cast<uint32_t*>(&h);
}

__global__ void __launch_bounds__(512) attn_kernel(const float* __restrict__ sims) {
  extern __shared__ float sm[];
  float* hs = sm;             // 40960 floats (160 rows x 256)
  float* ls = sm + 40960;     // 6656: wts/logits [64][4][26]
  float* sd = ls + 6656;      // 1664: simdot [64][26]
  float* ss = sd + 1664;      // 1440: sims halo [9][160]

  const int tid = threadIdx.x, lane = tid & 31, wid = tid >> 5;
  const int bw = blockIdx.x & 15;
  const int bh = (blockIdx.x >> 4) & 63;
  const int t = blockIdx.x >> 10;
  const int w0 = bw << 4, h0 = bh << 2;

  // ---- P0: k halo + sims halo ----
  const uint4* kq = (const uint4*)g_k;
  for (int i = tid; i < 10240; i += 512) {
    int cell = i >> 6, c4 = i & 63;
    int rr = cell / 20, cc = cell - rr * 20;
    int gh = min(max(h0 - 2 + rr, 0), 255);
    int gw = min(max(w0 - 2 + cc, 0), 255);
    ((uint4*)hs)[cell * 64 + c4] =
        kq[((size_t)((t << 16) | (gh << 8) | gw)) * 64 + c4];
  }
  for (int i = tid; i < 1440; i += 512) {
    int s = i / 160, cell = i - s * 160;
    int rr = cell / 20, cc = cell - rr * 20;
    int gh = min(max(h0 - 2 + rr, 0), 255);
    int gw = min(max(w0 - 2 + cc, 0), 255);
    ss[i] = sims[(size_t)(((t * 9 + s) << 16) | (gh << 8) | gw)];
  }
  __syncthreads();

  // ---- simdot [px][tap] ----
  for (int i = tid; i < 1600; i += 512) {
    int px = i / 25, tap = i - px * 25;
    int r = px >> 4, wc = px & 15;
    int di = tap / 5, dj = tap - di * 5;
    int ctr = (r + 2) * 20 + wc + 2;
    int nbc = (r + di) * 20 + wc + dj;
    float acc = 0.f;
#pragma unroll
    for (int s = 0; s < 9; ++s) acc += ss[s * 160 + ctr] * ss[s * 160 + nbc];
    sd[px * 26 + tap] = acc;
  }

  // ---- P1: logits ----
  const int r = wid & 3, seg = wid >> 2;
  const int hgrp = lane >> 3;
  const size_t pixg0 = (size_t)((t << 16) | ((h0 + r) << 8) | (w0 + (seg << 2)));
  const float4* qg = (const float4*)g_q;
  float4 qa[4], qb[4];
#pragma unroll
  for (int p = 0; p < 4; ++p) {
    qa[p] = qg[(pixg0 + p) * 64 + lane * 2];
    qb[p] = qg[(pixg0 + p) * 64 + lane * 2 + 1];
  }

#pragma unroll 1
  for (int di = 0; di < 5; ++di) {
#pragma unroll
    for (int j = 0; j < 8; ++j) {
      const float4* kr = (const float4*)(hs + ((r + di) * 20 + (seg << 2) + j) * 256);
      float4 ka = kr[lane * 2], kb = kr[lane * 2 + 1];
      const int plo = (j - 4 > 0) ? j - 4 : 0;
      const int phi = (j < 3) ? j : 3;
#pragma unroll
      for (int p = plo; p <= phi; ++p) {
        float d = qa[p].x * ka.x + qa[p].y * ka.y + qa[p].z * ka.z + qa[p].w * ka.w +
                  qb[p].x * kb.x + qb[p].y * kb.y + qb[p].z * kb.z + qb[p].w * kb.w;
        d += __shfl_xor_sync(0xffffffffu, d, 1);
        d += __shfl_xor_sync(0xffffffffu, d, 2);
        d += __shfl_xor_sync(0xffffffffu, d, 4);
        if ((lane & 7) == 0) {
          int px = (r << 4) + (seg << 2) + p;
          ls[(px * 4 + hgrp) * 26 + di * 5 + j - p] = d;
        }
      }
    }
  }
  __syncthreads();

  // ---- P1.5: softmax + sim reweight (in place in ls) ----
#pragma unroll 1
  for (int p = 0; p < 4; ++p) {
    const int px = (r << 4) + (seg << 2) + p;
#pragma unroll 1
    for (int h4 = 0; h4 < 4; ++h4) {
      float a = (lane < 25) ? ls[(px * 4 + h4) * 26 + lane] : -1e30f;
      float mx = a;
      mx = fmaxf(mx, __shfl_xor_sync(0xffffffffu, mx, 16));
      mx = fmaxf(mx, __shfl_xor_sync(0xffffffffu, mx, 8));
      mx = fmaxf(mx, __shfl_xor_sync(0xffffffffu, mx, 4));
      mx = fmaxf(mx, __shfl_xor_sync(0xffffffffu, mx, 2));
      mx = fmaxf(mx, __shfl_xor_sync(0xffffffffu, mx, 1));
      float e = (lane < 25) ? expf(a - mx) * sd[px * 26 + lane] : 0.f;
      float s = e;
      s += __shfl_xor_sync(0xffffffffu, s, 16);
      s += __shfl_xor_sync(0xffffffffu, s, 8);
      s += __shfl_xor_sync(0xffffffffu, s, 4);
      s += __shfl_xor_sync(0xffffffffu, s, 2);
      s += __shfl_xor_sync(0xffffffffu, s, 1);
      if (lane < 25) ls[(px * 4 + h4) * 26 + lane] = e / (1e-10f + s);
    }
  }
  __syncthreads();

  // ---- P2: v halo (overwrite hs) ----
  const uint4* vq = (const uint4*)g_v;
  for (int i = tid; i < 10240; i += 512) {
    int cell = i >> 6, c4 = i & 63;
    int rr = cell / 20, cc = cell - rr * 20;
    int gh = min(max(h0 - 2 + rr, 0), 255);
    int gw = min(max(w0 - 2 + cc, 0), 255);
    ((uint4*)hs)[cell * 64 + c4] =
        vq[((size_t)((t << 16) | (gh << 8) | gw)) * 64 + c4];
  }
  __syncthreads();

  // ---- P2: weighted accumulate ----
  float acc[4][8];
#pragma unroll
  for (int p = 0; p < 4; ++p)
#pragma unroll
    for (int c = 0; c < 8; ++c) acc[p][c] = 0.f;

#pragma unroll 1
  for (int di = 0; di < 5; ++di) {
#pragma unroll
    for (int j = 0; j < 8; ++j) {
      const float4* vr = (const float4*)(hs + ((r + di) * 20 + (seg << 2) + j) * 256);
      float4 va = vr[lane * 2], vb = vr[lane * 2 + 1];
      const int plo = (j - 4 > 0) ? j - 4 : 0;
      const int phi = (j < 3) ? j : 3;
#pragma unroll
      for (int p = plo; p <= phi; ++p) {
        int px = (r << 4) + (seg << 2) + p;
        float wt = ls[(px * 4 + hgrp) * 26 + di * 5 + j - p];
        acc[p][0] += wt * va.x; acc[p][1] += wt * va.y;
        acc[p][2] += wt * va.z; acc[p][3] += wt * va.w;
        acc[p][4] += wt * vb.x; acc[p][5] += wt * vb.y;
        acc[p][6] += wt * vb.z; acc[p][7] += wt * vb.w;
      }
    }
  }

  // ---- store g_o2 bf16 hi|lo directly (fused conv_o) ----
  uint4* oq = (uint4*)g_o2;
#pragma unroll
  for (int p = 0; p < 4; ++p) {
    float hi[8], lo[8];
#pragma unroll
    for (int c = 0; c < 8; ++c) {
      hi[c] = __bfloat162float(__float2bfloat16_rn(acc[p][c]));
      lo[c] = acc[p][c] - hi[c];
    }
    uint4 hv, lv;
    hv.x = packbf2(hi[0], hi[1]); hv.y = packbf2(hi[2], hi[3]);
    hv.z = packbf2(hi[4], hi[5]); hv.w = packbf2(hi[6], hi[7]);
    lv.x = packbf2(lo[0], lo[1]); lv.y = packbf2(lo[2], lo[3]);
    lv.z = packbf2(lo[4], lo[5]); lv.w = packbf2(lo[6], lo[7]);
    oq[(pixg0 + p) * 64 + lane] = hv;
    oq[(pixg0 + p) * 64 + 32 + lane] = lv;
  }
}

// ---------------------------------------------------------------------------
extern "C" void kernel_launch(void* const* d_in, const int* in_sizes, int n_in,
                              void* d_out, int out_size) {
  (void)in_sizes; (void)n_in; (void)out_size;
  const float* x = (const float*)d_in[0];
  const float* sims = (const float*)d_in[1];
  const float* Wq = (const float*)d_in[3];
  const float* Wk = (const float*)d_in[4];
  const float* Wv = (const float*)d_in[5];
  const float* Wp = (const float*)d_in[6];
  float* out = (float*)d_out;

  const int smem_cx = 256 * 65 * sizeof(float);
  const int smem_gm = 1024 + 163840 + 16896;
  const int smem_at = 50720 * sizeof(float);  // 202880 B
  cudaFuncSetAttribute(conv_x, cudaFuncAttributeMaxDynamicSharedMemorySize, smem_cx);
  cudaFuncSetAttribute(gemm_kernel, cudaFuncAttributeMaxDynamicSharedMemorySize, smem_gm);
  cudaFuncSetAttribute(attn_kernel, cudaFuncAttributeMaxDynamicSharedMemorySize, smem_at);

  __nv_bfloat16 *px2, *po2, *pw1, *pw2;
  cudaGetSymbolAddress((void**)&px2, g_x2);
  cudaGetSymbolAddress((void**)&po2, g_o2);
  cudaGetSymbolAddress((void**)&pw1, g_w1);
  cudaGetSymbolAddress((void**)&pw2, g_w2);

  conv_x<<<NPIX / 64, 256, smem_cx>>>(x);
  conv_w<<<1024, 256>>>(Wq, Wk, Wv, Wp);
  gemm_kernel<<<NPIX / 128, 256, smem_gm>>>(px2, pw1, nullptr, 0);
  attn_kernel<<<4096, 512, smem_at>>>(sims);
  gemm_kernel<<<NPIX / 128, 256, smem_gm>>>(po2, pw2, out, 1);
}